// round 5
// baseline (speedup 1.0000x reference)
#include <cuda_runtime.h>
#include <cuda_bf16.h>
#include <cstdint>
#include <math.h>

#define D 128
#define NMAX 100000
#define NPAD_MAX 100096
#define EMAX 1600000

// ---- scratch (static device globals; no runtime allocation) ----
static __device__ float g_h[(size_t)NMAX * D];                  // gathered ent rows
static __device__ __nv_bfloat16 g_Xhi[(size_t)NPAD_MAX * 256];  // X hi split
static __device__ __nv_bfloat16 g_Xlo[(size_t)NPAD_MAX * 256];  // X lo split
static __device__ __nv_bfloat16 g_B[512 * 768];                 // [n][ Bhi | Bhi | Blo ]
static __device__ float g_C[(size_t)NPAD_MAX * 512];            // GEMM result (gate preacts)
static __device__ float g_bias[512];                            // br, bz, bxn, bhh_n
static __device__ int g_deg[NPAD_MAX];
static __device__ int g_off[NPAD_MAX];
static __device__ int g_cursor[NPAD_MAX];
static __device__ int g_elist[EMAX];
static __device__ int g_total;

// ============================ PTX helpers (plain sm_103) ============================
__device__ __forceinline__ uint32_t smem_u32(const void* p) {
    uint32_t a;
    asm("{ .reg .u64 t; cvta.to.shared.u64 t, %1; cvt.u32.u64 %0, t; }" : "=r"(a) : "l"(p));
    return a;
}
__device__ __forceinline__ void cp_async16(uint32_t dst, const void* src) {
    asm volatile("cp.async.cg.shared.global [%0], [%1], 16;" :: "r"(dst), "l"(src));
}
__device__ __forceinline__ void ldm_x4(uint32_t* r, uint32_t addr) {
    asm volatile("ldmatrix.sync.aligned.m8n8.x4.shared.b16 {%0,%1,%2,%3}, [%4];"
                 : "=r"(r[0]), "=r"(r[1]), "=r"(r[2]), "=r"(r[3]) : "r"(addr));
}
__device__ __forceinline__ void mma_bf16(float* c, const uint32_t* a, uint32_t b0, uint32_t b1) {
    asm volatile(
        "mma.sync.aligned.m16n8k16.row.col.f32.bf16.bf16.f32 "
        "{%0,%1,%2,%3}, {%4,%5,%6,%7}, {%8,%9}, {%0,%1,%2,%3};"
        : "+f"(c[0]), "+f"(c[1]), "+f"(c[2]), "+f"(c[3])
        : "r"(a[0]), "r"(a[1]), "r"(a[2]), "r"(a[3]), "r"(b0), "r"(b1));
}
__device__ __forceinline__ float sigmoidf_(float x) { return 1.f / (1.f + expf(-x)); }

// ============================ prep: folded B (bf16 hi/lo) + biases ============================
__global__ void prep_kernel(const float* __restrict__ W, const float* __restrict__ w_ih,
                            const float* __restrict__ w_hh, const float* __restrict__ b_ih,
                            const float* __restrict__ b_hh) {
    int n = blockIdx.x;
    int k = threadIdx.x;
    if (n == 512) {
        if (k < 128) {
            g_bias[k]       = b_ih[k] + b_hh[k];
            g_bias[128 + k] = b_ih[128 + k] + b_hh[128 + k];
            g_bias[256 + k] = b_ih[256 + k];
            g_bias[384 + k] = b_hh[256 + k];
        }
        return;
    }
    float v;
    if (k < 128) {
        if (n < 384) {
            float acc = 0.f;
            for (int j = 0; j < 128; j++) acc = fmaf(W[k * 128 + j], w_ih[n * 256 + j], acc);
            v = acc;
        } else v = 0.f;
    } else {
        if (n < 256)      v = w_ih[n * 256 + k] + w_hh[n * 128 + (k - 128)];
        else if (n < 384) v = w_ih[n * 256 + k];
        else              v = w_hh[(n - 128) * 128 + (k - 128)];
    }
    __nv_bfloat16 hi = __float2bfloat16_rn(v);
    __nv_bfloat16 lo = __float2bfloat16_rn(v - __bfloat162float(hi));
    g_B[n * 768 + k] = hi;
    g_B[n * 768 + 256 + k] = hi;
    g_B[n * 768 + 512 + k] = lo;
}

// ============================ gather ============================
__global__ __launch_bounds__(256) void gather_kernel(const float* __restrict__ ent,
                                                     const int* __restrict__ node_id, int N) {
    int i = blockIdx.x * blockDim.x + threadIdx.x;
    int node = i >> 5, lane = i & 31;
    if (node >= N) return;
    int row = __ldg(node_id + node);
    reinterpret_cast<float4*>(g_h)[(size_t)node * 32 + lane] =
        __ldg(reinterpret_cast<const float4*>(ent) + (size_t)row * 32 + lane);
}

// ============================ CSR construction ============================
__global__ void zero_deg_kernel(int npad) {
    int i = blockIdx.x * blockDim.x + threadIdx.x;
    if (i < npad) g_deg[i] = 0;
    if (i == 0) g_total = 0;
}

__global__ void hist_kernel(const int* __restrict__ edst, int E) {
    int e = blockIdx.x * blockDim.x + threadIdx.x;
    if (e >= E) return;
    atomicAdd(&g_deg[__ldg(edst + e)], 1);
}

__global__ void offsets_kernel(int npad) {
    int i = blockIdx.x * blockDim.x + threadIdx.x;
    int lane = threadIdx.x & 31;
    int deg = (i < npad) ? g_deg[i] : 0;
    int run = deg;
    #pragma unroll
    for (int o = 1; o < 32; o <<= 1) {
        int v = __shfl_up_sync(0xFFFFFFFFu, run, o);
        if (lane >= o) run += v;
    }
    int total = __shfl_sync(0xFFFFFFFFu, run, 31);
    int base = 0;
    if (lane == 31) base = atomicAdd(&g_total, total);
    base = __shfl_sync(0xFFFFFFFFu, base, 31);
    int excl = base + run - deg;
    if (i < npad) { g_off[i] = excl; g_cursor[i] = excl; }
}

__global__ void fill_kernel(const int* __restrict__ esrc, const int* __restrict__ edst, int E) {
    int e = blockIdx.x * blockDim.x + threadIdx.x;
    if (e >= E) return;
    int d = __ldg(edst + e);
    int p = atomicAdd(&g_cursor[d], 1);
    g_elist[p] = __ldg(esrc + e);
}

// ============================ fused aggregate + build X (hi/lo bf16 split) ============
// Warp per node: pull edge list, accumulate g_h rows in registers, scale, split.
__global__ __launch_bounds__(256) void agg_buildx_kernel(const float* __restrict__ erb,
                                                         const float* __restrict__ onorm,
                                                         int N, int npad) {
    int gw = (int)((blockIdx.x * (size_t)blockDim.x + threadIdx.x) >> 5);
    int lane = threadIdx.x & 31;
    if (gw >= npad) return;
    float x[8];
    if (gw < N) {
        float4 acc = make_float4(0.f, 0.f, 0.f, 0.f);
        int off = __ldg(g_off + gw);
        int deg = __ldg(g_deg + gw);
        const float4* H = reinterpret_cast<const float4*>(g_h);
        int j = 0;
        for (; j + 4 <= deg; j += 4) {
            int s0 = __ldg(g_elist + off + j);
            int s1 = __ldg(g_elist + off + j + 1);
            int s2 = __ldg(g_elist + off + j + 2);
            int s3 = __ldg(g_elist + off + j + 3);
            float4 v0 = __ldg(H + (size_t)s0 * 32 + lane);
            float4 v1 = __ldg(H + (size_t)s1 * 32 + lane);
            float4 v2 = __ldg(H + (size_t)s2 * 32 + lane);
            float4 v3 = __ldg(H + (size_t)s3 * 32 + lane);
            acc.x += v0.x + v1.x + v2.x + v3.x;
            acc.y += v0.y + v1.y + v2.y + v3.y;
            acc.z += v0.z + v1.z + v2.z + v3.z;
            acc.w += v0.w + v1.w + v2.w + v3.w;
        }
        for (; j < deg; j++) {
            int s = __ldg(g_elist + off + j);
            float4 v = __ldg(H + (size_t)s * 32 + lane);
            acc.x += v.x; acc.y += v.y; acc.z += v.z; acc.w += v.w;
        }
        float sc = __ldg(onorm + gw);
        float4 e = __ldg(reinterpret_cast<const float4*>(erb) + (size_t)gw * 32 + lane);
        x[0] = acc.x * sc; x[1] = acc.y * sc; x[2] = acc.z * sc; x[3] = acc.w * sc;
        x[4] = e.x; x[5] = e.y; x[6] = e.z; x[7] = e.w;
    } else {
        #pragma unroll
        for (int q = 0; q < 8; q++) x[q] = 0.f;
    }
    unsigned short hs[8], ls[8];
    #pragma unroll
    for (int q = 0; q < 8; q++) {
        __nv_bfloat16 hb = __float2bfloat16_rn(x[q]);
        __nv_bfloat16 lb = __float2bfloat16_rn(x[q] - __bfloat162float(hb));
        hs[q] = *reinterpret_cast<unsigned short*>(&hb);
        ls[q] = *reinterpret_cast<unsigned short*>(&lb);
    }
    uint2* dhi0 = reinterpret_cast<uint2*>(g_Xhi + (size_t)gw * 256 + lane * 4);
    uint2* dhi1 = reinterpret_cast<uint2*>(g_Xhi + (size_t)gw * 256 + 128 + lane * 4);
    uint2* dlo0 = reinterpret_cast<uint2*>(g_Xlo + (size_t)gw * 256 + lane * 4);
    uint2* dlo1 = reinterpret_cast<uint2*>(g_Xlo + (size_t)gw * 256 + 128 + lane * 4);
    *dhi0 = make_uint2((uint32_t)hs[0] | ((uint32_t)hs[1] << 16), (uint32_t)hs[2] | ((uint32_t)hs[3] << 16));
    *dhi1 = make_uint2((uint32_t)hs[4] | ((uint32_t)hs[5] << 16), (uint32_t)hs[6] | ((uint32_t)hs[7] << 16));
    *dlo0 = make_uint2((uint32_t)ls[0] | ((uint32_t)ls[1] << 16), (uint32_t)ls[2] | ((uint32_t)ls[3] << 16));
    *dlo1 = make_uint2((uint32_t)ls[4] | ((uint32_t)ls[5] << 16), (uint32_t)ls[6] | ((uint32_t)ls[7] << 16));
}

// ============================ GEMM: C[npad,512] = Xv[npad,768] @ Bv[768,512]^T =========
#define STAGE_BYTES 32768
#define GEMM_SMEM (3 * STAGE_BYTES)

__global__ __launch_bounds__(256, 1) void gemm_kernel(int npad) {
    extern __shared__ char smc[];
    uint32_t sbase = smem_u32(smc);
    int tid = threadIdx.x, lane = tid & 31, w = tid >> 5;
    int n0 = blockIdx.x * 128;
    int d0 = blockIdx.y * 128;
    int wm = w & 3, wn = w >> 2;
    int m0 = wm * 32, nw0 = wn * 64;

    float acc[2][8][4];
    #pragma unroll
    for (int a = 0; a < 2; a++)
        #pragma unroll
        for (int b = 0; b < 8; b++)
            #pragma unroll
            for (int c = 0; c < 4; c++) acc[a][b][c] = 0.f;

    auto load_chunk = [&](int c, int st) {
        const __nv_bfloat16* X = (c >= 4 && c < 8) ? g_Xlo : g_Xhi;
        const __nv_bfloat16* Asrc = X + (size_t)n0 * 256 + (c & 3) * 64;
        const __nv_bfloat16* Bsrc = g_B + (size_t)d0 * 768 + c * 64;
        uint32_t abase = sbase + st * STAGE_BYTES;
        uint32_t bbase = abase + 16384;
        #pragma unroll
        for (int i = 0; i < 4; i++) {
            int e = i * 256 + tid;
            int row = e >> 3, ch = e & 7;
            cp_async16(abase + (row * 8 + (ch ^ (row & 7))) * 16,
                       Asrc + (size_t)row * 256 + ch * 8);
        }
        #pragma unroll
        for (int i = 0; i < 4; i++) {
            int e = i * 256 + tid;
            int row = e >> 3, ch = e & 7;
            cp_async16(bbase + (row * 8 + (ch ^ (row & 7))) * 16,
                       Bsrc + (size_t)row * 768 + ch * 8);
        }
        asm volatile("cp.async.commit_group;" ::: "memory");
    };

    load_chunk(0, 0);
    load_chunk(1, 1);

    for (int c = 0; c < 12; c++) {
        int st = c % 3;
        if (c < 10) asm volatile("cp.async.wait_group 1;" ::: "memory");
        else        asm volatile("cp.async.wait_group 0;" ::: "memory");
        __syncthreads();
        uint32_t abase = sbase + st * STAGE_BYTES;
        uint32_t bbase = abase + 16384;
        #pragma unroll
        for (int k16 = 0; k16 < 4; k16++) {
            uint32_t af[2][4], bf[4][4];
            #pragma unroll
            for (int mi = 0; mi < 2; mi++) {
                int row = m0 + mi * 16 + (lane & 15);
                int ch = k16 * 2 + (lane >> 4);
                ldm_x4(af[mi], abase + (row * 8 + (ch ^ (row & 7))) * 16);
            }
            #pragma unroll
            for (int j = 0; j < 4; j++) {
                int row = nw0 + j * 16 + (lane & 15);
                int ch = k16 * 2 + (lane >> 4);
                ldm_x4(bf[j], bbase + (row * 8 + (ch ^ (row & 7))) * 16);
            }
            #pragma unroll
            for (int mi = 0; mi < 2; mi++)
                #pragma unroll
                for (int j = 0; j < 4; j++) {
                    mma_bf16(acc[mi][2 * j],     af[mi], bf[j][0], bf[j][2]);
                    mma_bf16(acc[mi][2 * j + 1], af[mi], bf[j][1], bf[j][3]);
                }
        }
        __syncthreads();
        if (c + 2 < 12) load_chunk(c + 2, (c + 2) % 3);
    }

    int tr = lane >> 2, tc = (lane & 3) * 2;
    #pragma unroll
    for (int mi = 0; mi < 2; mi++) {
        #pragma unroll
        for (int j = 0; j < 8; j++) {
            int node = n0 + m0 + mi * 16 + tr;
            int d = d0 + nw0 + j * 8 + tc;
            float* cp = acc[mi][j];
            *reinterpret_cast<float2*>(g_C + (size_t)node * 512 + d) =
                make_float2(cp[0], cp[1]);
            *reinterpret_cast<float2*>(g_C + (size_t)(node + 8) * 512 + d) =
                make_float2(cp[2], cp[3]);
        }
    }
}

// ============================ epilogue: gates + relu + row norm ============================
__global__ __launch_bounds__(256) void epilogue_kernel(const float* __restrict__ erb,
                                                       float* __restrict__ out, int N) {
    int gw = (int)((blockIdx.x * (size_t)blockDim.x + threadIdx.x) >> 5);
    int lane = threadIdx.x & 31;
    if (gw >= N) return;
    const float4* C4 = reinterpret_cast<const float4*>(g_C + (size_t)gw * 512);
    float4 r4 = __ldg(C4 + lane);
    float4 z4 = __ldg(C4 + 32 + lane);
    float4 x4 = __ldg(C4 + 64 + lane);
    float4 h4 = __ldg(C4 + 96 + lane);
    float4 e4 = __ldg(reinterpret_cast<const float4*>(erb) + (size_t)gw * 32 + lane);
    const float* rr = &r4.x;
    const float* zz = &z4.x;
    const float* xx = &x4.x;
    const float* hh = &h4.x;
    const float* ee = &e4.x;
    float hv[4];
    float ss = 0.f;
    #pragma unroll
    for (int i = 0; i < 4; i++) {
        int d = lane * 4 + i;
        float r = sigmoidf_(rr[i] + __ldg(g_bias + d));
        float z = sigmoidf_(zz[i] + __ldg(g_bias + 128 + d));
        float nn = tanhf(xx[i] + __ldg(g_bias + 256 + d) + r * (hh[i] + __ldg(g_bias + 384 + d)));
        float h = fmaxf((1.f - z) * nn + z * ee[i], 0.f);
        ss += h * h;
        hv[i] = h;
    }
    #pragma unroll
    for (int o = 16; o; o >>= 1) ss += __shfl_xor_sync(0xFFFFFFFFu, ss, o);
    float inv = 1.f / fmaxf(sqrtf(ss), 1e-12f);
    reinterpret_cast<float4*>(out)[(size_t)gw * 32 + lane] =
        make_float4(hv[0] * inv, hv[1] * inv, hv[2] * inv, hv[3] * inv);
}

// ============================ launch ============================
extern "C" void kernel_launch(void* const* d_in, const int* in_sizes, int n_in,
                              void* d_out, int out_size) {
    const float* ent   = (const float*)d_in[0];
    const float* erb   = (const float*)d_in[2];
    const float* onorm = (const float*)d_in[3];
    const float* Wn    = (const float*)d_in[4];
    const float* w_ih  = (const float*)d_in[5];
    const float* w_hh  = (const float*)d_in[6];
    const float* b_ih  = (const float*)d_in[7];
    const float* b_hh  = (const float*)d_in[8];
    const int* node_id = (const int*)d_in[9];
    const int* esrc    = (const int*)d_in[10];
    const int* edst    = (const int*)d_in[11];
    int N = in_sizes[3];
    int E = in_sizes[10];
    float* out = (float*)d_out;
    int npad = ((N + 127) / 128) * 128;
    if (npad > NPAD_MAX) npad = NPAD_MAX;

    cudaFuncSetAttribute(gemm_kernel, cudaFuncAttributeMaxDynamicSharedMemorySize, GEMM_SMEM);

    prep_kernel<<<513, 256>>>(Wn, w_ih, w_hh, b_ih, b_hh);
    gather_kernel<<<(N * 32 + 255) / 256, 256>>>(ent, node_id, N);
    zero_deg_kernel<<<(npad + 255) / 256, 256>>>(npad);
    hist_kernel<<<(E + 255) / 256, 256>>>(edst, E);
    offsets_kernel<<<(npad + 255) / 256, 256>>>(npad);
    fill_kernel<<<(E + 255) / 256, 256>>>(esrc, edst, E);
    agg_buildx_kernel<<<(npad * 32 + 255) / 256, 256>>>(erb, onorm, N, npad);
    dim3 ggrid(npad / 128, 4);
    gemm_kernel<<<ggrid, 256, GEMM_SMEM>>>(npad);
    epilogue_kernel<<<(N * 32 + 255) / 256, 256>>>(erb, out, N);
}

// round 6
// speedup vs baseline: 1.2851x; 1.2851x over previous
#include <cuda_runtime.h>
#include <cuda_bf16.h>
#include <cstdint>
#include <math.h>

#define D 128
#define NMAX 100000
#define NPAD_MAX 100096

// ---- scratch (static device globals; no runtime allocation) ----
static __device__ float g_h[(size_t)NMAX * D];                  // gathered ent rows
static __device__ float g_agg[(size_t)NMAX * D];                // scatter-sum of g_h
static __device__ __nv_bfloat16 g_Xhi[(size_t)NPAD_MAX * 256];  // X hi split
static __device__ __nv_bfloat16 g_Xlo[(size_t)NPAD_MAX * 256];  // X lo split
static __device__ __nv_bfloat16 g_B[512 * 768];                 // [n][ Bhi | Bhi | Blo ]
static __device__ float g_C[(size_t)NPAD_MAX * 512];            // GEMM result (gate preacts)
static __device__ float g_bias[512];                            // br, bz, bxn, bhh_n

// ============================ PTX helpers (plain sm_103) ============================
__device__ __forceinline__ uint32_t smem_u32(const void* p) {
    uint32_t a;
    asm("{ .reg .u64 t; cvta.to.shared.u64 t, %1; cvt.u32.u64 %0, t; }" : "=r"(a) : "l"(p));
    return a;
}
__device__ __forceinline__ void cp_async16(uint32_t dst, const void* src) {
    asm volatile("cp.async.cg.shared.global [%0], [%1], 16;" :: "r"(dst), "l"(src));
}
__device__ __forceinline__ void ldm_x4(uint32_t* r, uint32_t addr) {
    asm volatile("ldmatrix.sync.aligned.m8n8.x4.shared.b16 {%0,%1,%2,%3}, [%4];"
                 : "=r"(r[0]), "=r"(r[1]), "=r"(r[2]), "=r"(r[3]) : "r"(addr));
}
__device__ __forceinline__ void mma_bf16(float* c, const uint32_t* a, uint32_t b0, uint32_t b1) {
    asm volatile(
        "mma.sync.aligned.m16n8k16.row.col.f32.bf16.bf16.f32 "
        "{%0,%1,%2,%3}, {%4,%5,%6,%7}, {%8,%9}, {%0,%1,%2,%3};"
        : "+f"(c[0]), "+f"(c[1]), "+f"(c[2]), "+f"(c[3])
        : "r"(a[0]), "r"(a[1]), "r"(a[2]), "r"(a[3]), "r"(b0), "r"(b1));
}
__device__ __forceinline__ float sigmoidf_(float x) { return 1.f / (1.f + expf(-x)); }

// ============================ prep: folded B (bf16 hi/lo) + biases ============================
__global__ void prep_kernel(const float* __restrict__ W, const float* __restrict__ w_ih,
                            const float* __restrict__ w_hh, const float* __restrict__ b_ih,
                            const float* __restrict__ b_hh) {
    int n = blockIdx.x;
    int k = threadIdx.x;
    if (n == 512) {
        if (k < 128) {
            g_bias[k]       = b_ih[k] + b_hh[k];
            g_bias[128 + k] = b_ih[128 + k] + b_hh[128 + k];
            g_bias[256 + k] = b_ih[256 + k];
            g_bias[384 + k] = b_hh[256 + k];
        }
        return;
    }
    float v;
    if (k < 128) {
        if (n < 384) {
            float acc = 0.f;
            for (int j = 0; j < 128; j++) acc = fmaf(W[k * 128 + j], w_ih[n * 256 + j], acc);
            v = acc;
        } else v = 0.f;
    } else {
        if (n < 256)      v = w_ih[n * 256 + k] + w_hh[n * 128 + (k - 128)];
        else if (n < 384) v = w_ih[n * 256 + k];
        else              v = w_hh[(n - 128) * 128 + (k - 128)];
    }
    __nv_bfloat16 hi = __float2bfloat16_rn(v);
    __nv_bfloat16 lo = __float2bfloat16_rn(v - __bfloat162float(hi));
    g_B[n * 768 + k] = hi;
    g_B[n * 768 + 256 + k] = hi;
    g_B[n * 768 + 512 + k] = lo;
}

// ============================ gather / zero / scatter ============================
__global__ __launch_bounds__(256) void gather_kernel(const float* __restrict__ ent,
                                                     const int* __restrict__ node_id, int N) {
    int i = blockIdx.x * blockDim.x + threadIdx.x;
    int node = i >> 5, lane = i & 31;
    if (node >= N) return;
    int row = __ldg(node_id + node);
    reinterpret_cast<float4*>(g_h)[(size_t)node * 32 + lane] =
        __ldg(reinterpret_cast<const float4*>(ent) + (size_t)row * 32 + lane);
}

__global__ void zero_kernel(int N) {
    size_t total = (size_t)N * 32;
    float4* p = reinterpret_cast<float4*>(g_agg);
    for (size_t i = blockIdx.x * (size_t)blockDim.x + threadIdx.x; i < total;
         i += (size_t)gridDim.x * blockDim.x)
        p[i] = make_float4(0.f, 0.f, 0.f, 0.f);
}

// 2 edges per warp: two independent row loads in flight per warp.
__global__ __launch_bounds__(256) void scatter_kernel(const int* __restrict__ esrc,
                                                      const int* __restrict__ edst, int E) {
    int warp = (int)((blockIdx.x * (size_t)blockDim.x + threadIdx.x) >> 5);
    int lane = threadIdx.x & 31;
    int e0 = warp * 2;
    if (e0 >= E) return;
    int s0 = __ldg(esrc + e0);
    int d0 = __ldg(edst + e0);
    bool has1 = (e0 + 1) < E;
    int s1 = has1 ? __ldg(esrc + e0 + 1) : 0;
    int d1 = has1 ? __ldg(edst + e0 + 1) : 0;
    float4 v0 = __ldg(reinterpret_cast<const float4*>(g_h) + (size_t)s0 * 32 + lane);
    float4 v1 = has1 ? __ldg(reinterpret_cast<const float4*>(g_h) + (size_t)s1 * 32 + lane)
                     : make_float4(0.f, 0.f, 0.f, 0.f);
    atomicAdd(reinterpret_cast<float4*>(g_agg) + (size_t)d0 * 32 + lane, v0);
    if (has1)
        atomicAdd(reinterpret_cast<float4*>(g_agg) + (size_t)d1 * 32 + lane, v1);
}

// ============================ build X (hi/lo bf16 split) ============================
__global__ __launch_bounds__(256) void build_x_kernel(const float* __restrict__ erb,
                                                      const float* __restrict__ onorm,
                                                      int N, int npad) {
    int i = blockIdx.x * blockDim.x + threadIdx.x;
    int node = i >> 5, lane = i & 31;
    if (node >= npad) return;
    float x[8];
    if (node < N) {
        float sc = __ldg(onorm + node);
        float4 a = __ldg(reinterpret_cast<const float4*>(g_agg) + (size_t)node * 32 + lane);
        float4 e = __ldg(reinterpret_cast<const float4*>(erb) + (size_t)node * 32 + lane);
        x[0] = a.x * sc; x[1] = a.y * sc; x[2] = a.z * sc; x[3] = a.w * sc;
        x[4] = e.x; x[5] = e.y; x[6] = e.z; x[7] = e.w;
    } else {
        #pragma unroll
        for (int q = 0; q < 8; q++) x[q] = 0.f;
    }
    unsigned short hs[8], ls[8];
    #pragma unroll
    for (int q = 0; q < 8; q++) {
        __nv_bfloat16 hb = __float2bfloat16_rn(x[q]);
        __nv_bfloat16 lb = __float2bfloat16_rn(x[q] - __bfloat162float(hb));
        hs[q] = *reinterpret_cast<unsigned short*>(&hb);
        ls[q] = *reinterpret_cast<unsigned short*>(&lb);
    }
    uint2* dhi0 = reinterpret_cast<uint2*>(g_Xhi + (size_t)node * 256 + lane * 4);
    uint2* dhi1 = reinterpret_cast<uint2*>(g_Xhi + (size_t)node * 256 + 128 + lane * 4);
    uint2* dlo0 = reinterpret_cast<uint2*>(g_Xlo + (size_t)node * 256 + lane * 4);
    uint2* dlo1 = reinterpret_cast<uint2*>(g_Xlo + (size_t)node * 256 + 128 + lane * 4);
    *dhi0 = make_uint2((uint32_t)hs[0] | ((uint32_t)hs[1] << 16), (uint32_t)hs[2] | ((uint32_t)hs[3] << 16));
    *dhi1 = make_uint2((uint32_t)hs[4] | ((uint32_t)hs[5] << 16), (uint32_t)hs[6] | ((uint32_t)hs[7] << 16));
    *dlo0 = make_uint2((uint32_t)ls[0] | ((uint32_t)ls[1] << 16), (uint32_t)ls[2] | ((uint32_t)ls[3] << 16));
    *dlo1 = make_uint2((uint32_t)ls[4] | ((uint32_t)ls[5] << 16), (uint32_t)ls[6] | ((uint32_t)ls[7] << 16));
}

// ============================ GEMM: C[npad,512] = Xv[npad,768] @ Bv[768,512]^T =========
// Virtual K chunks: 0-3 Xhi·Bhi, 4-7 Xlo·Bhi, 8-11 Xhi·Blo.
// For d0==384 (hn gate) B rows are exactly 0 for k<128 → only chunks {2,3,6,7,10,11}.
// 3-stage cp.async pipeline, 2 blocks/SM (192KB smem) for latency hiding.
#define STAGE_BYTES 32768
#define GEMM_SMEM (3 * STAGE_BYTES)

__global__ __launch_bounds__(256, 2) void gemm_kernel(int npad) {
    extern __shared__ char smc[];
    uint32_t sbase = smem_u32(smc);
    int tid = threadIdx.x, lane = tid & 31, w = tid >> 5;
    int n0 = blockIdx.x * 128;
    int d0 = blockIdx.y * 128;
    int wm = w & 3, wn = w >> 2;
    int m0 = wm * 32, nw0 = wn * 64;

    const int map3[6] = {2, 3, 6, 7, 10, 11};
    bool is_hn = (d0 == 384);
    int nch = is_hn ? 6 : 12;

    float acc[2][8][4];
    #pragma unroll
    for (int a = 0; a < 2; a++)
        #pragma unroll
        for (int b = 0; b < 8; b++)
            #pragma unroll
            for (int c = 0; c < 4; c++) acc[a][b][c] = 0.f;

    auto load_chunk = [&](int c, int st) {
        const __nv_bfloat16* X = (c >= 4 && c < 8) ? g_Xlo : g_Xhi;
        const __nv_bfloat16* Asrc = X + (size_t)n0 * 256 + (c & 3) * 64;
        const __nv_bfloat16* Bsrc = g_B + (size_t)d0 * 768 + c * 64;
        uint32_t abase = sbase + st * STAGE_BYTES;
        uint32_t bbase = abase + 16384;
        #pragma unroll
        for (int i = 0; i < 4; i++) {
            int e = i * 256 + tid;
            int row = e >> 3, ch = e & 7;
            cp_async16(abase + (row * 8 + (ch ^ (row & 7))) * 16,
                       Asrc + (size_t)row * 256 + ch * 8);
        }
        #pragma unroll
        for (int i = 0; i < 4; i++) {
            int e = i * 256 + tid;
            int row = e >> 3, ch = e & 7;
            cp_async16(bbase + (row * 8 + (ch ^ (row & 7))) * 16,
                       Bsrc + (size_t)row * 768 + ch * 8);
        }
        asm volatile("cp.async.commit_group;" ::: "memory");
    };

    auto chunk_of = [&](int i) { return is_hn ? map3[i] : i; };

    load_chunk(chunk_of(0), 0);
    load_chunk(chunk_of(1), 1);

    for (int i = 0; i < nch; i++) {
        int st = i % 3;
        if (i < nch - 1) asm volatile("cp.async.wait_group 1;" ::: "memory");
        else             asm volatile("cp.async.wait_group 0;" ::: "memory");
        __syncthreads();
        uint32_t abase = sbase + st * STAGE_BYTES;
        uint32_t bbase = abase + 16384;
        #pragma unroll
        for (int k16 = 0; k16 < 4; k16++) {
            uint32_t af[2][4], bf[4][4];
            #pragma unroll
            for (int mi = 0; mi < 2; mi++) {
                int row = m0 + mi * 16 + (lane & 15);
                int ch = k16 * 2 + (lane >> 4);
                ldm_x4(af[mi], abase + (row * 8 + (ch ^ (row & 7))) * 16);
            }
            #pragma unroll
            for (int j = 0; j < 4; j++) {
                int row = nw0 + j * 16 + (lane & 15);
                int ch = k16 * 2 + (lane >> 4);
                ldm_x4(bf[j], bbase + (row * 8 + (ch ^ (row & 7))) * 16);
            }
            #pragma unroll
            for (int mi = 0; mi < 2; mi++)
                #pragma unroll
                for (int j = 0; j < 4; j++) {
                    mma_bf16(acc[mi][2 * j],     af[mi], bf[j][0], bf[j][2]);
                    mma_bf16(acc[mi][2 * j + 1], af[mi], bf[j][1], bf[j][3]);
                }
        }
        __syncthreads();
        if (i + 2 < nch) load_chunk(chunk_of(i + 2), (i + 2) % 3);
    }

    int tr = lane >> 2, tc = (lane & 3) * 2;
    #pragma unroll
    for (int mi = 0; mi < 2; mi++) {
        #pragma unroll
        for (int j = 0; j < 8; j++) {
            int node = n0 + m0 + mi * 16 + tr;
            int d = d0 + nw0 + j * 8 + tc;
            float* cp = acc[mi][j];
            *reinterpret_cast<float2*>(g_C + (size_t)node * 512 + d) =
                make_float2(cp[0], cp[1]);
            *reinterpret_cast<float2*>(g_C + (size_t)(node + 8) * 512 + d) =
                make_float2(cp[2], cp[3]);
        }
    }
}

// ============================ epilogue: gates + relu + row norm ============================
__global__ __launch_bounds__(256) void epilogue_kernel(const float* __restrict__ erb,
                                                       float* __restrict__ out, int N) {
    int gw = (int)((blockIdx.x * (size_t)blockDim.x + threadIdx.x) >> 5);
    int lane = threadIdx.x & 31;
    if (gw >= N) return;
    const float4* C4 = reinterpret_cast<const float4*>(g_C + (size_t)gw * 512);
    float4 r4 = __ldg(C4 + lane);
    float4 z4 = __ldg(C4 + 32 + lane);
    float4 x4 = __ldg(C4 + 64 + lane);
    float4 h4 = __ldg(C4 + 96 + lane);
    float4 e4 = __ldg(reinterpret_cast<const float4*>(erb) + (size_t)gw * 32 + lane);
    const float* rr = &r4.x;
    const float* zz = &z4.x;
    const float* xx = &x4.x;
    const float* hh = &h4.x;
    const float* ee = &e4.x;
    float hv[4];
    float ss = 0.f;
    #pragma unroll
    for (int i = 0; i < 4; i++) {
        int d = lane * 4 + i;
        float r = sigmoidf_(rr[i] + __ldg(g_bias + d));
        float z = sigmoidf_(zz[i] + __ldg(g_bias + 128 + d));
        float nn = tanhf(xx[i] + __ldg(g_bias + 256 + d) + r * (hh[i] + __ldg(g_bias + 384 + d)));
        float h = fmaxf((1.f - z) * nn + z * ee[i], 0.f);
        ss += h * h;
        hv[i] = h;
    }
    #pragma unroll
    for (int o = 16; o; o >>= 1) ss += __shfl_xor_sync(0xFFFFFFFFu, ss, o);
    float inv = 1.f / fmaxf(sqrtf(ss), 1e-12f);
    reinterpret_cast<float4*>(out)[(size_t)gw * 32 + lane] =
        make_float4(hv[0] * inv, hv[1] * inv, hv[2] * inv, hv[3] * inv);
}

// ============================ launch ============================
extern "C" void kernel_launch(void* const* d_in, const int* in_sizes, int n_in,
                              void* d_out, int out_size) {
    const float* ent   = (const float*)d_in[0];
    const float* erb   = (const float*)d_in[2];
    const float* onorm = (const float*)d_in[3];
    const float* Wn    = (const float*)d_in[4];
    const float* w_ih  = (const float*)d_in[5];
    const float* w_hh  = (const float*)d_in[6];
    const float* b_ih  = (const float*)d_in[7];
    const float* b_hh  = (const float*)d_in[8];
    const int* node_id = (const int*)d_in[9];
    const int* esrc    = (const int*)d_in[10];
    const int* edst    = (const int*)d_in[11];
    int N = in_sizes[3];
    int E = in_sizes[10];
    float* out = (float*)d_out;
    int npad = ((N + 127) / 128) * 128;
    if (npad > NPAD_MAX) npad = NPAD_MAX;

    cudaFuncSetAttribute(gemm_kernel, cudaFuncAttributeMaxDynamicSharedMemorySize, GEMM_SMEM);

    prep_kernel<<<513, 256>>>(Wn, w_ih, w_hh, b_ih, b_hh);
    gather_kernel<<<(N * 32 + 255) / 256, 256>>>(ent, node_id, N);
    zero_kernel<<<512, 256>>>(N);
    int warps_needed = (E + 1) / 2;
    scatter_kernel<<<(warps_needed + 7) / 8, 256>>>(esrc, edst, E);
    build_x_kernel<<<(npad * 32 + 255) / 256, 256>>>(erb, onorm, N, npad);
    dim3 ggrid(npad / 128, 4);
    gemm_kernel<<<ggrid, 256, GEMM_SMEM>>>(npad);
    epilogue_kernel<<<(N * 32 + 255) / 256, 256>>>(erb, out, N);
}

// round 7
// speedup vs baseline: 1.3315x; 1.0360x over previous
#include <cuda_runtime.h>
#include <cuda_bf16.h>
#include <cstdint>
#include <math.h>

#define D 128
#define NMAX 100000
#define NPAD_MAX 100096

// ---- scratch (static device globals; no runtime allocation) ----
static __device__ float g_agg[(size_t)NMAX * D];                // scatter-sum of gathered rows
static __device__ __nv_bfloat16 g_Xhi[(size_t)NPAD_MAX * 256];  // X hi split
static __device__ __nv_bfloat16 g_Xlo[(size_t)NPAD_MAX * 256];  // X lo split
static __device__ __nv_bfloat16 g_B[512 * 768];                 // [n][ Bhi | Bhi | Blo ]
static __device__ float g_C[(size_t)NPAD_MAX * 512];            // GEMM result (gate preacts)
static __device__ float g_bias[512];                            // br, bz, bxn, bhh_n

// ============================ PTX helpers (plain sm_103) ============================
__device__ __forceinline__ uint32_t smem_u32(const void* p) {
    uint32_t a;
    asm("{ .reg .u64 t; cvta.to.shared.u64 t, %1; cvt.u32.u64 %0, t; }" : "=r"(a) : "l"(p));
    return a;
}
__device__ __forceinline__ void cp_async16(uint32_t dst, const void* src) {
    asm volatile("cp.async.cg.shared.global [%0], [%1], 16;" :: "r"(dst), "l"(src));
}
__device__ __forceinline__ void ldm_x4(uint32_t* r, uint32_t addr) {
    asm volatile("ldmatrix.sync.aligned.m8n8.x4.shared.b16 {%0,%1,%2,%3}, [%4];"
                 : "=r"(r[0]), "=r"(r[1]), "=r"(r[2]), "=r"(r[3]) : "r"(addr));
}
__device__ __forceinline__ void mma_bf16(float* c, const uint32_t* a, uint32_t b0, uint32_t b1) {
    asm volatile(
        "mma.sync.aligned.m16n8k16.row.col.f32.bf16.bf16.f32 "
        "{%0,%1,%2,%3}, {%4,%5,%6,%7}, {%8,%9}, {%0,%1,%2,%3};"
        : "+f"(c[0]), "+f"(c[1]), "+f"(c[2]), "+f"(c[3])
        : "r"(a[0]), "r"(a[1]), "r"(a[2]), "r"(a[3]), "r"(b0), "r"(b1));
}
__device__ __forceinline__ float sigmoidf_(float x) { return 1.f / (1.f + expf(-x)); }

// ============================ prep: folded B (bf16 hi/lo) + biases ============================
__global__ void prep_kernel(const float* __restrict__ W, const float* __restrict__ w_ih,
                            const float* __restrict__ w_hh, const float* __restrict__ b_ih,
                            const float* __restrict__ b_hh) {
    int n = blockIdx.x;
    int k = threadIdx.x;
    if (n == 512) {
        if (k < 128) {
            g_bias[k]       = b_ih[k] + b_hh[k];
            g_bias[128 + k] = b_ih[128 + k] + b_hh[128 + k];
            g_bias[256 + k] = b_ih[256 + k];
            g_bias[384 + k] = b_hh[256 + k];
        }
        return;
    }
    float v;
    if (k < 128) {
        if (n < 384) {
            float acc = 0.f;
            for (int j = 0; j < 128; j++) acc = fmaf(W[k * 128 + j], w_ih[n * 256 + j], acc);
            v = acc;
        } else v = 0.f;
    } else {
        if (n < 256)      v = w_ih[n * 256 + k] + w_hh[n * 128 + (k - 128)];
        else if (n < 384) v = w_ih[n * 256 + k];
        else              v = w_hh[(n - 128) * 128 + (k - 128)];
    }
    __nv_bfloat16 hi = __float2bfloat16_rn(v);
    __nv_bfloat16 lo = __float2bfloat16_rn(v - __bfloat162float(hi));
    g_B[n * 768 + k] = hi;
    g_B[n * 768 + 256 + k] = hi;
    g_B[n * 768 + 512 + k] = lo;
}

// ============================ zero / scatter ============================
__global__ void zero_kernel(int N) {
    size_t total = (size_t)N * 32;
    float4* p = reinterpret_cast<float4*>(g_agg);
    for (size_t i = blockIdx.x * (size_t)blockDim.x + threadIdx.x; i < total;
         i += (size_t)gridDim.x * blockDim.x)
        p[i] = make_float4(0.f, 0.f, 0.f, 0.f);
}

// 4 edges per warp; reads ent rows directly via node_id indirection (no g_h staging).
__global__ __launch_bounds__(256) void scatter_kernel(const float* __restrict__ ent,
                                                      const int* __restrict__ node_id,
                                                      const int* __restrict__ esrc,
                                                      const int* __restrict__ edst, int E) {
    int warp = (int)((blockIdx.x * (size_t)blockDim.x + threadIdx.x) >> 5);
    int lane = threadIdx.x & 31;
    int e0 = warp * 4;
    if (e0 >= E) return;
    int dst[4], row[4];
    #pragma unroll
    for (int j = 0; j < 4; j++) {
        if (e0 + j < E) {
            int s = __ldg(esrc + e0 + j);
            dst[j] = __ldg(edst + e0 + j);
            row[j] = __ldg(node_id + s);
        } else {
            dst[j] = -1; row[j] = 0;
        }
    }
    float4 v[4];
    #pragma unroll
    for (int j = 0; j < 4; j++)
        v[j] = __ldg(reinterpret_cast<const float4*>(ent) + (size_t)row[j] * 32 + lane);
    #pragma unroll
    for (int j = 0; j < 4; j++)
        if (dst[j] >= 0)
            atomicAdd(reinterpret_cast<float4*>(g_agg) + (size_t)dst[j] * 32 + lane, v[j]);
}

// ============================ build X (hi/lo bf16 split) ============================
__global__ __launch_bounds__(256) void build_x_kernel(const float* __restrict__ erb,
                                                      const float* __restrict__ onorm,
                                                      int N, int npad) {
    int i = blockIdx.x * blockDim.x + threadIdx.x;
    int node = i >> 5, lane = i & 31;
    if (node >= npad) return;
    float x[8];
    if (node < N) {
        float sc = __ldg(onorm + node);
        float4 a = __ldg(reinterpret_cast<const float4*>(g_agg) + (size_t)node * 32 + lane);
        float4 e = __ldg(reinterpret_cast<const float4*>(erb) + (size_t)node * 32 + lane);
        x[0] = a.x * sc; x[1] = a.y * sc; x[2] = a.z * sc; x[3] = a.w * sc;
        x[4] = e.x; x[5] = e.y; x[6] = e.z; x[7] = e.w;
    } else {
        #pragma unroll
        for (int q = 0; q < 8; q++) x[q] = 0.f;
    }
    unsigned short hs[8], ls[8];
    #pragma unroll
    for (int q = 0; q < 8; q++) {
        __nv_bfloat16 hb = __float2bfloat16_rn(x[q]);
        __nv_bfloat16 lb = __float2bfloat16_rn(x[q] - __bfloat162float(hb));
        hs[q] = *reinterpret_cast<unsigned short*>(&hb);
        ls[q] = *reinterpret_cast<unsigned short*>(&lb);
    }
    uint2* dhi0 = reinterpret_cast<uint2*>(g_Xhi + (size_t)node * 256 + lane * 4);
    uint2* dhi1 = reinterpret_cast<uint2*>(g_Xhi + (size_t)node * 256 + 128 + lane * 4);
    uint2* dlo0 = reinterpret_cast<uint2*>(g_Xlo + (size_t)node * 256 + lane * 4);
    uint2* dlo1 = reinterpret_cast<uint2*>(g_Xlo + (size_t)node * 256 + 128 + lane * 4);
    *dhi0 = make_uint2((uint32_t)hs[0] | ((uint32_t)hs[1] << 16), (uint32_t)hs[2] | ((uint32_t)hs[3] << 16));
    *dhi1 = make_uint2((uint32_t)hs[4] | ((uint32_t)hs[5] << 16), (uint32_t)hs[6] | ((uint32_t)hs[7] << 16));
    *dlo0 = make_uint2((uint32_t)ls[0] | ((uint32_t)ls[1] << 16), (uint32_t)ls[2] | ((uint32_t)ls[3] << 16));
    *dlo1 = make_uint2((uint32_t)ls[4] | ((uint32_t)ls[5] << 16), (uint32_t)ls[6] | ((uint32_t)ls[7] << 16));
}

// ============================ GEMM: C[npad,512] = Xv[npad,768] @ Bv[768,512]^T =========
// Virtual K chunks: 0-3 Xhi·Bhi, 4-7 Xlo·Bhi, 8-11 Xhi·Blo.
// hn gate (d0==384): B rows exactly 0 for k<128 → only chunks {2,3,6,7,10,11}.
// 3-stage cp.async pipeline, ONE barrier per stage (load issued before compute).
#define STAGE_BYTES 32768
#define GEMM_SMEM (3 * STAGE_BYTES)

__global__ __launch_bounds__(256, 2) void gemm_kernel(int npad) {
    extern __shared__ char smc[];
    uint32_t sbase = smem_u32(smc);
    int tid = threadIdx.x, lane = tid & 31, w = tid >> 5;
    int n0 = blockIdx.x * 128;
    int d0 = blockIdx.y * 128;
    int wm = w & 3, wn = w >> 2;
    int m0 = wm * 32, nw0 = wn * 64;

    const int map3[6] = {2, 3, 6, 7, 10, 11};
    bool is_hn = (d0 == 384);
    int nch = is_hn ? 6 : 12;

    float acc[2][8][4];
    #pragma unroll
    for (int a = 0; a < 2; a++)
        #pragma unroll
        for (int b = 0; b < 8; b++)
            #pragma unroll
            for (int c = 0; c < 4; c++) acc[a][b][c] = 0.f;

    auto load_chunk = [&](int c, int st) {
        const __nv_bfloat16* X = (c >= 4 && c < 8) ? g_Xlo : g_Xhi;
        const __nv_bfloat16* Asrc = X + (size_t)n0 * 256 + (c & 3) * 64;
        const __nv_bfloat16* Bsrc = g_B + (size_t)d0 * 768 + c * 64;
        uint32_t abase = sbase + st * STAGE_BYTES;
        uint32_t bbase = abase + 16384;
        #pragma unroll
        for (int i = 0; i < 4; i++) {
            int e = i * 256 + tid;
            int row = e >> 3, ch = e & 7;
            cp_async16(abase + (row * 8 + (ch ^ (row & 7))) * 16,
                       Asrc + (size_t)row * 256 + ch * 8);
        }
        #pragma unroll
        for (int i = 0; i < 4; i++) {
            int e = i * 256 + tid;
            int row = e >> 3, ch = e & 7;
            cp_async16(bbase + (row * 8 + (ch ^ (row & 7))) * 16,
                       Bsrc + (size_t)row * 768 + ch * 8);
        }
        asm volatile("cp.async.commit_group;" ::: "memory");
    };

    auto chunk_of = [&](int i) { return is_hn ? map3[i] : i; };

    load_chunk(chunk_of(0), 0);
    load_chunk(chunk_of(1), 1);

    for (int i = 0; i < nch; i++) {
        int st = i % 3;
        if (i < nch - 1) asm volatile("cp.async.wait_group 1;" ::: "memory");
        else             asm volatile("cp.async.wait_group 0;" ::: "memory");
        __syncthreads();
        // safe: barrier above proves all warps finished reading stage (i+2)%3
        // (last read at iteration i-1); load doesn't touch stage i%3 or (i+1)%3.
        if (i + 2 < nch) load_chunk(chunk_of(i + 2), (i + 2) % 3);
        uint32_t abase = sbase + st * STAGE_BYTES;
        uint32_t bbase = abase + 16384;
        #pragma unroll
        for (int k16 = 0; k16 < 4; k16++) {
            uint32_t af[2][4], bf[4][4];
            #pragma unroll
            for (int mi = 0; mi < 2; mi++) {
                int row = m0 + mi * 16 + (lane & 15);
                int ch = k16 * 2 + (lane >> 4);
                ldm_x4(af[mi], abase + (row * 8 + (ch ^ (row & 7))) * 16);
            }
            #pragma unroll
            for (int j = 0; j < 4; j++) {
                int row = nw0 + j * 16 + (lane & 15);
                int ch = k16 * 2 + (lane >> 4);
                ldm_x4(bf[j], bbase + (row * 8 + (ch ^ (row & 7))) * 16);
            }
            #pragma unroll
            for (int mi = 0; mi < 2; mi++)
                #pragma unroll
                for (int j = 0; j < 4; j++) {
                    mma_bf16(acc[mi][2 * j],     af[mi], bf[j][0], bf[j][2]);
                    mma_bf16(acc[mi][2 * j + 1], af[mi], bf[j][1], bf[j][3]);
                }
        }
    }

    int tr = lane >> 2, tc = (lane & 3) * 2;
    #pragma unroll
    for (int mi = 0; mi < 2; mi++) {
        #pragma unroll
        for (int j = 0; j < 8; j++) {
            int node = n0 + m0 + mi * 16 + tr;
            int d = d0 + nw0 + j * 8 + tc;
            float* cp = acc[mi][j];
            *reinterpret_cast<float2*>(g_C + (size_t)node * 512 + d) =
                make_float2(cp[0], cp[1]);
            *reinterpret_cast<float2*>(g_C + (size_t)(node + 8) * 512 + d) =
                make_float2(cp[2], cp[3]);
        }
    }
}

// ============================ epilogue: gates + relu + row norm ============================
__global__ __launch_bounds__(256) void epilogue_kernel(const float* __restrict__ erb,
                                                       float* __restrict__ out, int N) {
    int gw = (int)((blockIdx.x * (size_t)blockDim.x + threadIdx.x) >> 5);
    int lane = threadIdx.x & 31;
    if (gw >= N) return;
    const float4* C4 = reinterpret_cast<const float4*>(g_C + (size_t)gw * 512);
    float4 r4 = __ldg(C4 + lane);
    float4 z4 = __ldg(C4 + 32 + lane);
    float4 x4 = __ldg(C4 + 64 + lane);
    float4 h4 = __ldg(C4 + 96 + lane);
    float4 e4 = __ldg(reinterpret_cast<const float4*>(erb) + (size_t)gw * 32 + lane);
    const float* rr = &r4.x;
    const float* zz = &z4.x;
    const float* xx = &x4.x;
    const float* hh = &h4.x;
    const float* ee = &e4.x;
    float hv[4];
    float ss = 0.f;
    #pragma unroll
    for (int i = 0; i < 4; i++) {
        int d = lane * 4 + i;
        float r = sigmoidf_(rr[i] + __ldg(g_bias + d));
        float z = sigmoidf_(zz[i] + __ldg(g_bias + 128 + d));
        float nn = tanhf(xx[i] + __ldg(g_bias + 256 + d) + r * (hh[i] + __ldg(g_bias + 384 + d)));
        float h = fmaxf((1.f - z) * nn + z * ee[i], 0.f);
        ss += h * h;
        hv[i] = h;
    }
    #pragma unroll
    for (int o = 16; o; o >>= 1) ss += __shfl_xor_sync(0xFFFFFFFFu, ss, o);
    float inv = 1.f / fmaxf(sqrtf(ss), 1e-12f);
    reinterpret_cast<float4*>(out)[(size_t)gw * 32 + lane] =
        make_float4(hv[0] * inv, hv[1] * inv, hv[2] * inv, hv[3] * inv);
}

// ============================ launch ============================
extern "C" void kernel_launch(void* const* d_in, const int* in_sizes, int n_in,
                              void* d_out, int out_size) {
    const float* ent   = (const float*)d_in[0];
    const float* erb   = (const float*)d_in[2];
    const float* onorm = (const float*)d_in[3];
    const float* Wn    = (const float*)d_in[4];
    const float* w_ih  = (const float*)d_in[5];
    const float* w_hh  = (const float*)d_in[6];
    const float* b_ih  = (const float*)d_in[7];
    const float* b_hh  = (const float*)d_in[8];
    const int* node_id = (const int*)d_in[9];
    const int* esrc    = (const int*)d_in[10];
    const int* edst    = (const int*)d_in[11];
    int N = in_sizes[3];
    int E = in_sizes[10];
    float* out = (float*)d_out;
    int npad = ((N + 127) / 128) * 128;
    if (npad > NPAD_MAX) npad = NPAD_MAX;

    cudaFuncSetAttribute(gemm_kernel, cudaFuncAttributeMaxDynamicSharedMemorySize, GEMM_SMEM);

    prep_kernel<<<513, 256>>>(Wn, w_ih, w_hh, b_ih, b_hh);
    zero_kernel<<<512, 256>>>(N);
    int warps_needed = (E + 3) / 4;
    scatter_kernel<<<(warps_needed + 7) / 8, 256>>>(ent, node_id, esrc, edst, E);
    build_x_kernel<<<(npad * 32 + 255) / 256, 256>>>(erb, onorm, N, npad);
    dim3 ggrid(npad / 128, 4);
    gemm_kernel<<<ggrid, 256, GEMM_SMEM>>>(npad);
    epilogue_kernel<<<(N * 32 + 255) / 256, 256>>>(erb, out, N);
}